// round 13
// baseline (speedup 1.0000x reference)
#include <cuda_runtime.h>
#include <cuda_fp16.h>
#include <cstdint>

#define N 8192
#define D 128
#define NB 64                 // 64 blocks of 128 rows/cols
#define STRB 272              // smem tile row stride bytes (136 halfs)

// dynamic smem layout (bytes)
#define SM_A     0            // 128*272 = 34816
#define SM_B0    34816        // 34816 (also col-scratch overlay when dead)
#define SM_B1    69632        // 34816
#define SM_SQR   104448       // 128 floats
#define SM_SQC0  104960       // 128 floats
#define SM_SQC1  105472       // 128 floats
#define SM_P2    105984       // 128*3 uints = 1536
#define SM_TOTAL 107520

__device__ __half   g_xh[N * D];
__device__ float    g_sq[N];            // ||x||^2 + 512
__device__ uint32_t g_keys[N][NB][3];   // per (row, block): top-3 slot keys
__device__ float    g_partial[1024];
__device__ unsigned g_cnt = 0;

__device__ __forceinline__ bool better(float d1, int i1, float d2, int i2) {
    return (d1 < d2) || (d1 == d2 && i1 < i2);
}
__device__ __forceinline__ uint32_t smem_u32(const void* p) {
    uint32_t a;
    asm("{ .reg .u64 t; cvta.to.shared.u64 t, %1; cvt.u32.u64 %0, t; }" : "=r"(a) : "l"(p));
    return a;
}
__device__ __forceinline__ void ldsm_x4(uint32_t* r, uint32_t addr) {
    asm volatile("ldmatrix.sync.aligned.m8n8.x4.shared.b16 {%0,%1,%2,%3}, [%4];"
                 : "=r"(r[0]), "=r"(r[1]), "=r"(r[2]), "=r"(r[3]) : "r"(addr));
}
// fp16-accumulator HMMA: d (2 regs = 4 halfs) = a*b + d
__device__ __forceinline__ void mma16816h(uint32_t* d, const uint32_t* a, uint32_t b0, uint32_t b1) {
    asm volatile("mma.sync.aligned.m16n8k16.row.col.f16.f16.f16.f16 "
                 "{%0,%1}, {%2,%3,%4,%5}, {%6,%7}, {%0,%1};"
                 : "+r"(d[0]), "+r"(d[1])
                 : "r"(a[0]), "r"(a[1]), "r"(a[2]), "r"(a[3]), "r"(b0), "r"(b1));
}
__device__ __forceinline__ void cp_async16(uint32_t dst, const void* src) {
    asm volatile("cp.async.cg.shared.global [%0], [%1], 16;" :: "r"(dst), "l"(src));
}
__device__ __forceinline__ void cp_commit() { asm volatile("cp.async.commit_group;" ::: "memory"); }
__device__ __forceinline__ void cp_wait1() { asm volatile("cp.async.wait_group 1;" ::: "memory"); }
__device__ __forceinline__ void cp_wait0() { asm volatile("cp.async.wait_group 0;" ::: "memory"); }

__device__ __forceinline__ void ins3(uint32_t c, uint32_t* t) {
#pragma unroll
    for (int s = 0; s < 3; s++) {
        uint32_t lo = min(t[s], c);
        c = max(t[s], c);
        t[s] = lo;
    }
}
__device__ __forceinline__ float2 h2f(uint32_t v) {
    return __half22float2(*reinterpret_cast<__half2*>(&v));
}

// ---------------------------------------------------------------------------
// Kernel P: fp16 cast + (row norm + 512)
// ---------------------------------------------------------------------------
__global__ void prep_kernel(const float* __restrict__ x) {
    int row  = blockIdx.x * 8 + (threadIdx.x >> 5);
    int lane = threadIdx.x & 31;
    const float* xr = x + row * D;
    float s = 0.f;
#pragma unroll
    for (int kk = 0; kk < 4; kk++) {
        int k = lane + 32 * kk;
        float v = xr[k];
        g_xh[row * D + k] = __float2half_rn(v);
        s = fmaf(v, v, s);
    }
#pragma unroll
    for (int o = 16; o; o >>= 1) s += __shfl_xor_sync(0xffffffffu, s, o);
    if (lane == 0) g_sq[row] = s + 512.0f;
}

// ---------------------------------------------------------------------------
// gram helpers
// ---------------------------------------------------------------------------
__device__ __forceinline__ void mma_tile(uint32_t aBase, uint32_t bBase, uint32_t (&acc)[16][2]) {
#pragma unroll
    for (int nf = 0; nf < 16; nf++) { acc[nf][0] = 0u; acc[nf][1] = 0u; }
#pragma unroll
    for (int ks = 0; ks < 8; ks++) {
        uint32_t a[4];
        ldsm_x4(a, aBase + ks * 32);
#pragma unroll
        for (int nf4 = 0; nf4 < 8; nf4++) {
            uint32_t b[4];
            ldsm_x4(b, bBase + (uint32_t)(nf4 * 16 * STRB) + ks * 32);
            mma16816h(acc[nf4 * 2],     a, b[0], b[1]);
            mma16816h(acc[nf4 * 2 + 1], a, b[2], b[3]);
        }
    }
}

// Row-side quad slots {b,b+1,b+8,b+9}; col-side (I<J) 4-row slots {r,r+4,r+8,r+12}.
__device__ __forceinline__ void epilogue_tile(
    uint32_t (&acc)[16][2], char* sm, int I, int J,
    int w, int l, int tid, const float* sqC_sm, float sqRh0, float sqRh1)
{
    const int lane2 = l & 3;

    // ---- row-side ----
    uint32_t kd[2][3];
#pragma unroll
    for (int h = 0; h < 2; h++)
#pragma unroll
        for (int s = 0; s < 3; s++) kd[h][s] = 0xFFFFFFFFu;

#pragma unroll
    for (int t8 = 0; t8 < 8; t8++) {
        float2 sjA = *(const float2*)&sqC_sm[t8 * 16 + lane2 * 2];
        float2 sjB = *(const float2*)&sqC_sm[t8 * 16 + 8 + lane2 * 2];
        const uint32_t idb = (uint32_t)((t8 << 2) | lane2);
        float2 fA[2], fB[2];
        fA[0] = h2f(acc[2 * t8][0]);     fA[1] = h2f(acc[2 * t8][1]);
        fB[0] = h2f(acc[2 * t8 + 1][0]); fB[1] = h2f(acc[2 * t8 + 1][1]);
#pragma unroll
        for (int h = 0; h < 2; h++) {
            float k0 = fmaf(-2.f, fA[h].x, sjA.x);
            float k1 = fmaf(-2.f, fA[h].y, sjA.y);
            float k2 = fmaf(-2.f, fB[h].x, sjB.x);
            float k3 = fmaf(-2.f, fB[h].y, sjB.y);
            float m = fminf(fminf(k0, k1), fminf(k2, k3));
            ins3((__float_as_uint(m) & 0xFFFFFF80u) | idb, kd[h]);
        }
    }
#pragma unroll
    for (int h = 0; h < 2; h++) {
#pragma unroll
        for (int off = 1; off < 4; off <<= 1) {
            uint32_t o[3];
#pragma unroll
            for (int s = 0; s < 3; s++) o[s] = __shfl_xor_sync(0xffffffffu, kd[h][s], off);
#pragma unroll
            for (int s = 0; s < 3; s++) ins3(o[s], kd[h]);
        }
    }
    if (lane2 == 0) {
#pragma unroll
        for (int h = 0; h < 2; h++) {
            int row = I * 128 + w * 16 + (l >> 2) + h * 8;
#pragma unroll
            for (int s = 0; s < 3; s++) g_keys[row][J][s] = kd[h][s];
        }
    }

    // ---- col-side ----
    if (I < J) {
        __syncthreads();   // all ldsm reads of this tile done; B0 overlay safe
        uint32_t* cscr = (uint32_t*)(sm + SM_B0);      // [128 cols][33]
        const uint32_t id5 = (uint32_t)((w << 2) | (l >> 2));   // valid for l<16
#pragma unroll
        for (int nf = 0; nf < 16; nf++) {
            float2 g0 = h2f(acc[nf][0]);   // row h=0, cols 0/1
            float2 g1 = h2f(acc[nf][1]);   // row h=1, cols 0/1
#pragma unroll
            for (int q = 0; q < 2; q++) {
                int c = nf * 8 + lane2 * 2 + q;
                float d0 = q ? g0.y : g0.x;
                float d1 = q ? g1.y : g1.x;
                float kk = fminf(fmaf(-2.f, d0, sqRh0), fmaf(-2.f, d1, sqRh1));
                kk = fminf(kk, __shfl_xor_sync(0xffffffffu, kk, 16));
                if (!(l & 16))
                    cscr[c * 33 + id5] = (__float_as_uint(kk) & 0xFFFFFF80u) | id5;
            }
        }
        __syncthreads();

        int c = tid & 127, half = tid >> 7;
        uint32_t t3[3] = {0xFFFFFFFFu, 0xFFFFFFFFu, 0xFFFFFFFFu};
#pragma unroll
        for (int k = 0; k < 16; k++) ins3(cscr[c * 33 + half * 16 + k], t3);
        uint32_t* p2 = (uint32_t*)(sm + SM_P2);
        if (half == 1) {
#pragma unroll
            for (int s = 0; s < 3; s++) p2[c * 3 + s] = t3[s];
        }
        __syncthreads();
        if (half == 0) {
#pragma unroll
            for (int s = 0; s < 3; s++) ins3(p2[c * 3 + s], t3);
            int col = J * 128 + c;
#pragma unroll
            for (int s = 0; s < 3; s++) g_keys[col][I][s] = t3[s];
        }
    }
}

// ---------------------------------------------------------------------------
// Kernel B: paired triangular tiles. 1024 pair-CTAs (tiles (I,J0),(I,J0+1),
// shared A, double-buffered B) launched first, then 32 single-tile CTAs.
// ---------------------------------------------------------------------------
__global__ __launch_bounds__(256, 2) void gram_top_kernel() {
    extern __shared__ char sm[];
    const uint32_t smBase = smem_u32(sm);
    float* sqR_sm  = (float*)(sm + SM_SQR);
    float* sqC0_sm = (float*)(sm + SM_SQC0);
    float* sqC1_sm = (float*)(sm + SM_SQC1);

    const int tid = threadIdx.x;
    const int w = tid >> 5, l = tid & 31;

    int b = blockIdx.x, I = 0, J0, nT;
    if (b < 1024) {
        while (b >= ((NB - I) >> 1)) { b -= (NB - I) >> 1; I++; }
        J0 = I + 2 * b; nT = 2;
    } else {
        I = 2 * (b - 1024) + 1; J0 = NB - 1; nT = 1;
    }

    // group 0: A + B0
    {
        const __half* Ag = g_xh + I  * 128 * D;
        const __half* Bg = g_xh + J0 * 128 * D;
#pragma unroll
        for (int v = 0; v < 8; v++) {
            int i = tid + v * 256;
            int r = i >> 4, c16 = i & 15;
            cp_async16(smBase + SM_A  + (uint32_t)(r * STRB + c16 * 16), Ag + r * D + c16 * 8);
            cp_async16(smBase + SM_B0 + (uint32_t)(r * STRB + c16 * 16), Bg + r * D + c16 * 8);
        }
        cp_commit();
        if (tid < 128) sqR_sm[tid] = g_sq[I * 128 + tid];
        else           sqC0_sm[tid - 128] = g_sq[J0 * 128 + tid - 128];
    }
    // group 1: B1 (pairs only)
    if (nT == 2) {
        const __half* Bg = g_xh + (J0 + 1) * 128 * D;
#pragma unroll
        for (int v = 0; v < 8; v++) {
            int i = tid + v * 256;
            int r = i >> 4, c16 = i & 15;
            cp_async16(smBase + SM_B1 + (uint32_t)(r * STRB + c16 * 16), Bg + r * D + c16 * 8);
        }
        cp_commit();
        if (tid < 128) sqC1_sm[tid] = g_sq[(J0 + 1) * 128 + tid];
        cp_wait1();
    } else {
        cp_wait0();
    }
    __syncthreads();

    const uint32_t aBase  = smBase + SM_A  + (uint32_t)((w * 16 + (l & 15)) * STRB) + ((l >> 4) & 1) * 16;
    const uint32_t bOffL  = (uint32_t)(((l & 7) + ((l >> 4) & 1) * 8) * STRB) + ((l >> 3) & 1) * 16;
    const float sqRh0 = sqR_sm[w * 16 + (l >> 2)];
    const float sqRh1 = sqR_sm[w * 16 + (l >> 2) + 8];

    uint32_t acc[16][2];
    mma_tile(aBase, smBase + SM_B0 + bOffL, acc);
    epilogue_tile(acc, sm, I, J0, w, l, tid, sqC0_sm, sqRh0, sqRh1);

    if (nT == 2) {
        cp_wait0();
        __syncthreads();
        mma_tile(aBase, smBase + SM_B1 + bOffL, acc);
        epilogue_tile(acc, sm, I, J0 + 1, w, l, tid, sqC1_sm, sqRh0, sqRh1);
    }
}

// ---------------------------------------------------------------------------
// Kernel C: 5th-smallest slot key over 192, threshold, expand members,
// two-phase exact rescore (batched d^2, lane-parallel select), hinge, mean.
// ---------------------------------------------------------------------------
__global__ void finalize_kernel(const float* __restrict__ x, const float* __restrict__ p,
                                float* __restrict__ out) {
    __shared__ int   memb[8][96];
    __shared__ float md2[8][96];
    __shared__ float shw[8];
    __shared__ float shr[256];
    __shared__ bool  amLast;
    int w    = threadIdx.x >> 5;
    int lane = threadIdx.x & 31;
    int row  = blockIdx.x * 8 + w;
    int Jr   = row >> 7;

    const uint32_t* kp = &g_keys[row][0][0];   // 192 keys
    uint32_t k[6];
#pragma unroll
    for (int v = 0; v < 6; v++) k[v] = kp[lane + 32 * v];

    // 5 extraction rounds -> 5th-smallest slot key
    uint32_t a[6], gm = 0;
#pragma unroll
    for (int v = 0; v < 6; v++) a[v] = k[v];
#pragma unroll
    for (int r = 0; r < 5; r++) {
        uint32_t mv = a[0];
#pragma unroll
        for (int v = 1; v < 6; v++) mv = min(mv, a[v]);
#pragma unroll
        for (int o = 16; o; o >>= 1) mv = min(mv, __shfl_xor_sync(0xffffffffu, mv, o));
        gm = mv;
#pragma unroll
        for (int v = 0; v < 6; v++) if (a[v] == gm) a[v] = 0xFFFFFFFFu;
    }
    float thr = __uint_as_float(gm & 0xFFFFFF80u) + 2.5f;   // widened for fp16 accum

    // compact passing slots -> expand 4 member cols each
    uint32_t ltm = (1u << lane) - 1u;
    int cnt = 0;
#pragma unroll
    for (int v = 0; v < 6; v++) {
        bool pass = __uint_as_float(k[v] & 0xFFFFFF80u) <= thr;
        uint32_t bal = __ballot_sync(0xffffffffu, pass);
        if (pass) {
            int pos = cnt + __popc(bal & ltm);
            if (pos < 24) {
                int kpos = lane + 32 * v;
                int bb = kpos / 3;
                uint32_t id = k[v] & 0x7Fu;
                if (bb >= Jr) {   // row-side quad: {0,1,8,9}
                    int base = bb * 128 + (int)((id >> 2) & 7) * 16 + (int)(id & 3) * 2;
                    memb[w][4 * pos + 0] = base;
                    memb[w][4 * pos + 1] = base + 1;
                    memb[w][4 * pos + 2] = base + 8;
                    memb[w][4 * pos + 3] = base + 9;
                } else {          // col-side 4-row: {0,4,8,12}
                    int base = bb * 128 + (int)((id >> 2) & 7) * 16 + (int)(id & 3);
                    memb[w][4 * pos + 0] = base;
                    memb[w][4 * pos + 1] = base + 4;
                    memb[w][4 * pos + 2] = base + 8;
                    memb[w][4 * pos + 3] = base + 12;
                }
            }
        }
        cnt += __popc(bal);
    }
    int mcnt = 4 * min(cnt, 24);
    __syncwarp();

    float4 xi = ((const float4*)(x + row * D))[lane];

    // phase A: exact d^2 for all members, 2-way interleaved reductions
    for (int i = 0; i < mcnt; i += 2) {
        int j0 = memb[w][i];
        int j1 = memb[w][(i + 1 < mcnt) ? i + 1 : i];
        float4 xa = ((const float4*)(x + j0 * D))[lane];
        float4 xb = ((const float4*)(x + j1 * D))[lane];
        float a0 = xi.x - xa.x, a1 = xi.y - xa.y, a2 = xi.z - xa.z, a3 = xi.w - xa.w;
        float b0 = xi.x - xb.x, b1 = xi.y - xb.y, b2 = xi.z - xb.z, b3 = xi.w - xb.w;
        float s0 = fmaf(a0, a0, fmaf(a1, a1, fmaf(a2, a2, a3 * a3)));
        float s1 = fmaf(b0, b0, fmaf(b1, b1, fmaf(b2, b2, b3 * b3)));
#pragma unroll
        for (int o = 16; o; o >>= 1) {
            s0 += __shfl_xor_sync(0xffffffffu, s0, o);
            s1 += __shfl_xor_sync(0xffffffffu, s1, o);
        }
        if (lane == 0) {
            md2[w][i] = s0;
            if (i + 1 < mcnt) md2[w][i + 1] = s1;
        }
    }
    __syncwarp();

    // phase B: lane-parallel top-5 + butterfly merge
    float t5d[5]; int t5i[5];
#pragma unroll
    for (int s = 0; s < 5; s++) { t5d[s] = __int_as_float(0x7f800000); t5i[s] = 0x7fffffff; }
    for (int i = lane; i < mcnt; i += 32) {
        float d2 = fmaxf(md2[w][i], 1e-12f);
        int j = memb[w][i];
        if (better(d2, j, t5d[4], t5i[4])) {
            float cd = d2; int ci = j;
#pragma unroll
            for (int s = 0; s < 5; s++) {
                if (better(cd, ci, t5d[s], t5i[s])) {
                    float td = t5d[s]; t5d[s] = cd; cd = td;
                    int   ti = t5i[s]; t5i[s] = ci; ci = ti;
                }
            }
        }
    }
#pragma unroll
    for (int off = 1; off < 32; off <<= 1) {
        float od[5]; int oi[5];
#pragma unroll
        for (int s = 0; s < 5; s++) {
            od[s] = __shfl_xor_sync(0xffffffffu, t5d[s], off);
            oi[s] = __shfl_xor_sync(0xffffffffu, t5i[s], off);
        }
        float ad[5]; int ai[5];
#pragma unroll
        for (int s = 0; s < 5; s++) { ad[s] = t5d[s]; ai[s] = t5i[s]; }
        int ia = 0, ib = 0;
#pragma unroll
        for (int s = 0; s < 5; s++) {
            bool ta = better(ad[ia], ai[ia], od[ib], oi[ib]);
            t5d[s] = ta ? ad[ia] : od[ib];
            t5i[s] = ta ? ai[ia] : oi[ib];
            if (ta) ia++; else ib++;
        }
    }
    int neg = t5i[4];

    float4 pi = ((const float4*)(p + row * D))[lane];
    float4 xn = ((const float4*)(x + neg * D))[lane];
    float ap0 = xi.x - pi.x + 1e-6f, ap1 = xi.y - pi.y + 1e-6f;
    float ap2 = xi.z - pi.z + 1e-6f, ap3 = xi.w - pi.w + 1e-6f;
    float an0 = xi.x - xn.x + 1e-6f, an1 = xi.y - xn.y + 1e-6f;
    float an2 = xi.z - xn.z + 1e-6f, an3 = xi.w - xn.w + 1e-6f;
    float sap = fmaf(ap0, ap0, fmaf(ap1, ap1, fmaf(ap2, ap2, ap3 * ap3)));
    float san = fmaf(an0, an0, fmaf(an1, an1, fmaf(an2, an2, an3 * an3)));
#pragma unroll
    for (int o = 16; o; o >>= 1) {
        sap += __shfl_xor_sync(0xffffffffu, sap, o);
        san += __shfl_xor_sync(0xffffffffu, san, o);
    }
    if (lane == 0)
        shw[w] = fmaxf(sqrtf(sap) - sqrtf(san) + 0.3f, 0.f);
    __syncthreads();

    if (threadIdx.x == 0) {
        float s = 0.f;
#pragma unroll
        for (int i = 0; i < 8; i++) s += shw[i];
        g_partial[blockIdx.x] = s;
    }
    __threadfence();
    if (threadIdx.x == 0)
        amLast = (atomicInc(&g_cnt, 1023u) == 1023u);
    __syncthreads();

    if (amLast) {
        float s = 0.f;
        for (int i = threadIdx.x; i < 1024; i += 256) s += g_partial[i];
        shr[threadIdx.x] = s;
        __syncthreads();
        for (int o = 128; o; o >>= 1) {
            if (threadIdx.x < o) shr[threadIdx.x] += shr[threadIdx.x + o];
            __syncthreads();
        }
        if (threadIdx.x == 0) out[0] = shr[0] * (1.0f / N);
    }
}

// ---------------------------------------------------------------------------
extern "C" void kernel_launch(void* const* d_in, const int* in_sizes, int n_in,
                              void* d_out, int out_size) {
    const float* x   = (const float*)d_in[0];
    const float* pos = (const float*)d_in[1];
    float* out = (float*)d_out;

    cudaFuncSetAttribute(gram_top_kernel,
                         cudaFuncAttributeMaxDynamicSharedMemorySize, SM_TOTAL);

    prep_kernel<<<N / 8, 256>>>(x);
    gram_top_kernel<<<1056, 256, SM_TOTAL>>>();
    finalize_kernel<<<N / 8, 256>>>(x, pos, out);
}

// round 14
// speedup vs baseline: 1.5576x; 1.5576x over previous
#include <cuda_runtime.h>
#include <cuda_fp16.h>
#include <cstdint>

#define N 8192
#define D 128
#define NB 64                 // 64 blocks of 128 rows/cols
#define NTRI 2080             // NB*(NB+1)/2 tiles
#define STRB 272              // smem tile row stride bytes (136 halfs)

// dynamic smem layout (bytes)
#define SM_A     0            // 128*272 = 34816 (col-scratch overlay after MMA)
#define SM_B     34816        // 34816
#define SM_SQR   69632        // 128 floats
#define SM_SQC   70144        // 128 floats
#define SM_P2    70656        // 128*3 uints = 1536
#define SM_TOTAL 72192

__device__ __half   g_xh[N * D];
__device__ float    g_sq[N];            // ||x||^2 + 512
__device__ uint32_t g_keys[N][NB][3];   // per (row, block): top-3 slot keys
__device__ float    g_partial[1024];
__device__ unsigned g_cnt = 0;

__device__ __forceinline__ bool better(float d1, int i1, float d2, int i2) {
    return (d1 < d2) || (d1 == d2 && i1 < i2);
}
__device__ __forceinline__ uint32_t smem_u32(const void* p) {
    uint32_t a;
    asm("{ .reg .u64 t; cvta.to.shared.u64 t, %1; cvt.u32.u64 %0, t; }" : "=r"(a) : "l"(p));
    return a;
}
__device__ __forceinline__ void ldsm_x4(uint32_t* r, uint32_t addr) {
    asm volatile("ldmatrix.sync.aligned.m8n8.x4.shared.b16 {%0,%1,%2,%3}, [%4];"
                 : "=r"(r[0]), "=r"(r[1]), "=r"(r[2]), "=r"(r[3]) : "r"(addr));
}
__device__ __forceinline__ void mma16816(float* d, const uint32_t* a, uint32_t b0, uint32_t b1) {
    asm volatile("mma.sync.aligned.m16n8k16.row.col.f32.f16.f16.f32 "
                 "{%0,%1,%2,%3}, {%4,%5,%6,%7}, {%8,%9}, {%0,%1,%2,%3};"
                 : "+f"(d[0]), "+f"(d[1]), "+f"(d[2]), "+f"(d[3])
                 : "r"(a[0]), "r"(a[1]), "r"(a[2]), "r"(a[3]), "r"(b0), "r"(b1));
}
__device__ __forceinline__ void cp_async16(uint32_t dst, const void* src) {
    asm volatile("cp.async.cg.shared.global [%0], [%1], 16;" :: "r"(dst), "l"(src));
}
__device__ __forceinline__ void cp_commit() { asm volatile("cp.async.commit_group;" ::: "memory"); }
__device__ __forceinline__ void cp_wait0() { asm volatile("cp.async.wait_group 0;" ::: "memory"); }

__device__ __forceinline__ void ins3(uint32_t c, uint32_t* t) {
#pragma unroll
    for (int s = 0; s < 3; s++) {
        uint32_t lo = min(t[s], c);
        c = max(t[s], c);
        t[s] = lo;
    }
}

// ---------------------------------------------------------------------------
// Kernel P: fp16 cast + (row norm + 512)
// ---------------------------------------------------------------------------
__global__ void prep_kernel(const float* __restrict__ x) {
    int row  = blockIdx.x * 8 + (threadIdx.x >> 5);
    int lane = threadIdx.x & 31;
    const float* xr = x + row * D;
    float s = 0.f;
#pragma unroll
    for (int kk = 0; kk < 4; kk++) {
        int k = lane + 32 * kk;
        float v = xr[k];
        g_xh[row * D + k] = __float2half_rn(v);
        s = fmaf(v, v, s);
    }
#pragma unroll
    for (int o = 16; o; o >>= 1) s += __shfl_xor_sync(0xffffffffu, s, o);
    if (lane == 0) g_sq[row] = s + 512.0f;
}

// ---------------------------------------------------------------------------
// Kernel B: triangular fp16 Gram tiles (I<=J), dual-side slot selection.
// 2080 CTAs x 256 threads (8 warps, each 16 rows x 128 cols).
// Row-side: quad-slots {b,b+1,b+8,b+9}. Col-side (I<J): 4-row slots
// {r,r+4,r+8,r+12} via xor-16 pre-min. Key = bits(sq_p+512-2dot)|id.
// ---------------------------------------------------------------------------
__global__ __launch_bounds__(256, 2) void gram_top_kernel() {
    extern __shared__ char sm[];
    const uint32_t smBase = smem_u32(sm);
    float* sqR_sm = (float*)(sm + SM_SQR);
    float* sqC_sm = (float*)(sm + SM_SQC);

    const int tid = threadIdx.x;
    const int w = tid >> 5, l = tid & 31;
    const int lane2 = l & 3;

    // triangular tile index -> (I, J)
    int t = blockIdx.x, I = 0;
    while (t >= NB - I) { t -= NB - I; I++; }
    const int J = I + t;

    // load A (rows block I) and B (cols block J): 128 rows x 256 B each
    {
        const __half* Ag = g_xh + I * 128 * D;
        const __half* Bg = g_xh + J * 128 * D;
#pragma unroll
        for (int v = 0; v < 8; v++) {
            int i = tid + v * 256;            // 2048 16B chunks each
            int r = i >> 4, c16 = i & 15;
            cp_async16(smBase + SM_A + (uint32_t)(r * STRB + c16 * 16), Ag + r * D + c16 * 8);
            cp_async16(smBase + SM_B + (uint32_t)(r * STRB + c16 * 16), Bg + r * D + c16 * 8);
        }
        cp_commit();
        if (tid < 128) sqR_sm[tid] = g_sq[I * 128 + tid];
        else           sqC_sm[tid - 128] = g_sq[J * 128 + tid - 128];
        cp_wait0();
    }
    __syncthreads();

    // MMA: 16 rows x 128 cols per warp
    const uint32_t aBase = smBase + SM_A + (uint32_t)((w * 16 + (l & 15)) * STRB) + ((l >> 4) & 1) * 16;
    const uint32_t bBase = smBase + SM_B + (uint32_t)(((l & 7) + ((l >> 4) & 1) * 8) * STRB) + ((l >> 3) & 1) * 16;

    float acc[16][4];
#pragma unroll
    for (int nf = 0; nf < 16; nf++)
#pragma unroll
        for (int q = 0; q < 4; q++) acc[nf][q] = 0.f;

#pragma unroll
    for (int ks = 0; ks < 8; ks++) {
        uint32_t a[4];
        ldsm_x4(a, aBase + ks * 32);
#pragma unroll
        for (int nf4 = 0; nf4 < 8; nf4++) {
            uint32_t b[4];
            ldsm_x4(b, bBase + (uint32_t)(nf4 * 16 * STRB) + ks * 32);
            mma16816(acc[nf4 * 2],     a, b[0], b[1]);
            mma16816(acc[nf4 * 2 + 1], a, b[2], b[3]);
        }
    }

    const float sqRh0 = sqR_sm[w * 16 + (l >> 2)];
    const float sqRh1 = sqR_sm[w * 16 + (l >> 2) + 8];

    // ---- row-side: quad-slots {base, +1, +8, +9}, base = t8*16 + lane2*2 ----
    uint32_t kd[2][3];
#pragma unroll
    for (int h = 0; h < 2; h++)
#pragma unroll
        for (int s = 0; s < 3; s++) kd[h][s] = 0xFFFFFFFFu;

#pragma unroll
    for (int t8 = 0; t8 < 8; t8++) {
        float2 sjA = *(const float2*)&sqC_sm[t8 * 16 + lane2 * 2];
        float2 sjB = *(const float2*)&sqC_sm[t8 * 16 + 8 + lane2 * 2];
        const uint32_t idb = (uint32_t)((t8 << 2) | lane2);
#pragma unroll
        for (int h = 0; h < 2; h++) {
            float k0 = fmaf(-2.f, acc[2 * t8][h * 2 + 0], sjA.x);
            float k1 = fmaf(-2.f, acc[2 * t8][h * 2 + 1], sjA.y);
            float k2 = fmaf(-2.f, acc[2 * t8 + 1][h * 2 + 0], sjB.x);
            float k3 = fmaf(-2.f, acc[2 * t8 + 1][h * 2 + 1], sjB.y);
            float m = fminf(fminf(k0, k1), fminf(k2, k3));
            ins3((__float_as_uint(m) & 0xFFFFFF80u) | idb, kd[h]);
        }
    }
#pragma unroll
    for (int h = 0; h < 2; h++) {
#pragma unroll
        for (int off = 1; off < 4; off <<= 1) {
            uint32_t o[3];
#pragma unroll
            for (int s = 0; s < 3; s++) o[s] = __shfl_xor_sync(0xffffffffu, kd[h][s], off);
#pragma unroll
            for (int s = 0; s < 3; s++) ins3(o[s], kd[h]);
        }
    }
    if (lane2 == 0) {
#pragma unroll
        for (int h = 0; h < 2; h++) {
            int row = I * 128 + w * 16 + (l >> 2) + h * 8;
#pragma unroll
            for (int s = 0; s < 3; s++) g_keys[row][J][s] = kd[h][s];
        }
    }

    // ---- col-side (I < J): 4-row slots {r, r+4, r+8, r+12} via xor-16 pre-min ----
    if (I < J) {
        __syncthreads();   // all ldsm reads done; A overlay safe
        uint32_t* cscr = (uint32_t*)(sm + SM_A);       // [128 cols][33]
        const uint32_t id5 = (uint32_t)((w << 2) | (l >> 2));   // valid for l<16
#pragma unroll
        for (int nf = 0; nf < 16; nf++)
#pragma unroll
            for (int q = 0; q < 2; q++) {
                int c = nf * 8 + lane2 * 2 + q;
                float kk = fminf(fmaf(-2.f, acc[nf][q],     sqRh0),
                                 fmaf(-2.f, acc[nf][2 + q], sqRh1));
                kk = fminf(kk, __shfl_xor_sync(0xffffffffu, kk, 16));
                if (!(l & 16))
                    cscr[c * 33 + id5] = (__float_as_uint(kk) & 0xFFFFFF80u) | id5;
            }
        __syncthreads();

        int c = tid & 127, half = tid >> 7;
        uint32_t t3[3] = {0xFFFFFFFFu, 0xFFFFFFFFu, 0xFFFFFFFFu};
#pragma unroll
        for (int k = 0; k < 16; k++) ins3(cscr[c * 33 + half * 16 + k], t3);
        uint32_t* p2 = (uint32_t*)(sm + SM_P2);
        if (half == 1) {
#pragma unroll
            for (int s = 0; s < 3; s++) p2[c * 3 + s] = t3[s];
        }
        __syncthreads();
        if (half == 0) {
#pragma unroll
            for (int s = 0; s < 3; s++) ins3(p2[c * 3 + s], t3);
            int col = J * 128 + c;
#pragma unroll
            for (int s = 0; s < 3; s++) g_keys[col][I][s] = t3[s];
        }
    }
}

// ---------------------------------------------------------------------------
// Kernel C: 5th-smallest slot key over 192, threshold, expand members,
// two-phase exact rescore (batched d^2, lane-parallel select), hinge, mean.
// ---------------------------------------------------------------------------
__global__ void finalize_kernel(const float* __restrict__ x, const float* __restrict__ p,
                                float* __restrict__ out) {
    __shared__ int   memb[8][96];
    __shared__ float md2[8][96];
    __shared__ float shw[8];
    __shared__ float shr[256];
    __shared__ bool  amLast;
    int w    = threadIdx.x >> 5;
    int lane = threadIdx.x & 31;
    int row  = blockIdx.x * 8 + w;
    int Jr   = row >> 7;

    const uint32_t* kp = &g_keys[row][0][0];   // 192 keys
    uint32_t k[6];
#pragma unroll
    for (int v = 0; v < 6; v++) k[v] = kp[lane + 32 * v];

    // 5 extraction rounds -> 5th-smallest slot key
    uint32_t a[6], gm = 0;
#pragma unroll
    for (int v = 0; v < 6; v++) a[v] = k[v];
#pragma unroll
    for (int r = 0; r < 5; r++) {
        uint32_t mv = a[0];
#pragma unroll
        for (int v = 1; v < 6; v++) mv = min(mv, a[v]);
#pragma unroll
        for (int o = 16; o; o >>= 1) mv = min(mv, __shfl_xor_sync(0xffffffffu, mv, o));
        gm = mv;
#pragma unroll
        for (int v = 0; v < 6; v++) if (a[v] == gm) a[v] = 0xFFFFFFFFu;
    }
    float thr = __uint_as_float(gm & 0xFFFFFF80u) + 1.0f;

    // compact passing slots -> expand 4 member cols each
    uint32_t ltm = (1u << lane) - 1u;
    int cnt = 0;
#pragma unroll
    for (int v = 0; v < 6; v++) {
        bool pass = __uint_as_float(k[v] & 0xFFFFFF80u) <= thr;
        uint32_t bal = __ballot_sync(0xffffffffu, pass);
        if (pass) {
            int pos = cnt + __popc(bal & ltm);
            if (pos < 24) {
                int kpos = lane + 32 * v;
                int bb = kpos / 3;
                uint32_t id = k[v] & 0x7Fu;
                if (bb >= Jr) {   // row-side quad: {0,1,8,9}
                    int base = bb * 128 + (int)((id >> 2) & 7) * 16 + (int)(id & 3) * 2;
                    memb[w][4 * pos + 0] = base;
                    memb[w][4 * pos + 1] = base + 1;
                    memb[w][4 * pos + 2] = base + 8;
                    memb[w][4 * pos + 3] = base + 9;
                } else {          // col-side 4-row: {0,4,8,12}
                    int base = bb * 128 + (int)((id >> 2) & 7) * 16 + (int)(id & 3);
                    memb[w][4 * pos + 0] = base;
                    memb[w][4 * pos + 1] = base + 4;
                    memb[w][4 * pos + 2] = base + 8;
                    memb[w][4 * pos + 3] = base + 12;
                }
            }
        }
        cnt += __popc(bal);
    }
    int mcnt = 4 * min(cnt, 24);
    __syncwarp();

    float4 xi = ((const float4*)(x + row * D))[lane];

    // phase A: exact d^2 for all members, 2-way interleaved reductions
    for (int i = 0; i < mcnt; i += 2) {
        int j0 = memb[w][i];
        int j1 = memb[w][(i + 1 < mcnt) ? i + 1 : i];
        float4 xa = ((const float4*)(x + j0 * D))[lane];
        float4 xb = ((const float4*)(x + j1 * D))[lane];
        float a0 = xi.x - xa.x, a1 = xi.y - xa.y, a2 = xi.z - xa.z, a3 = xi.w - xa.w;
        float b0 = xi.x - xb.x, b1 = xi.y - xb.y, b2 = xi.z - xb.z, b3 = xi.w - xb.w;
        float s0 = fmaf(a0, a0, fmaf(a1, a1, fmaf(a2, a2, a3 * a3)));
        float s1 = fmaf(b0, b0, fmaf(b1, b1, fmaf(b2, b2, b3 * b3)));
#pragma unroll
        for (int o = 16; o; o >>= 1) {
            s0 += __shfl_xor_sync(0xffffffffu, s0, o);
            s1 += __shfl_xor_sync(0xffffffffu, s1, o);
        }
        if (lane == 0) {
            md2[w][i] = s0;
            if (i + 1 < mcnt) md2[w][i + 1] = s1;
        }
    }
    __syncwarp();

    // phase B: lane-parallel top-5 + butterfly merge
    float t5d[5]; int t5i[5];
#pragma unroll
    for (int s = 0; s < 5; s++) { t5d[s] = __int_as_float(0x7f800000); t5i[s] = 0x7fffffff; }
    for (int i = lane; i < mcnt; i += 32) {
        float d2 = fmaxf(md2[w][i], 1e-12f);
        int j = memb[w][i];
        if (better(d2, j, t5d[4], t5i[4])) {
            float cd = d2; int ci = j;
#pragma unroll
            for (int s = 0; s < 5; s++) {
                if (better(cd, ci, t5d[s], t5i[s])) {
                    float td = t5d[s]; t5d[s] = cd; cd = td;
                    int   ti = t5i[s]; t5i[s] = ci; ci = ti;
                }
            }
        }
    }
#pragma unroll
    for (int off = 1; off < 32; off <<= 1) {
        float od[5]; int oi[5];
#pragma unroll
        for (int s = 0; s < 5; s++) {
            od[s] = __shfl_xor_sync(0xffffffffu, t5d[s], off);
            oi[s] = __shfl_xor_sync(0xffffffffu, t5i[s], off);
        }
        float ad[5]; int ai[5];
#pragma unroll
        for (int s = 0; s < 5; s++) { ad[s] = t5d[s]; ai[s] = t5i[s]; }
        int ia = 0, ib = 0;
#pragma unroll
        for (int s = 0; s < 5; s++) {
            bool ta = better(ad[ia], ai[ia], od[ib], oi[ib]);
            t5d[s] = ta ? ad[ia] : od[ib];
            t5i[s] = ta ? ai[ia] : oi[ib];
            if (ta) ia++; else ib++;
        }
    }
    int neg = t5i[4];

    float4 pi = ((const float4*)(p + row * D))[lane];
    float4 xn = ((const float4*)(x + neg * D))[lane];
    float ap0 = xi.x - pi.x + 1e-6f, ap1 = xi.y - pi.y + 1e-6f;
    float ap2 = xi.z - pi.z + 1e-6f, ap3 = xi.w - pi.w + 1e-6f;
    float an0 = xi.x - xn.x + 1e-6f, an1 = xi.y - xn.y + 1e-6f;
    float an2 = xi.z - xn.z + 1e-6f, an3 = xi.w - xn.w + 1e-6f;
    float sap = fmaf(ap0, ap0, fmaf(ap1, ap1, fmaf(ap2, ap2, ap3 * ap3)));
    float san = fmaf(an0, an0, fmaf(an1, an1, fmaf(an2, an2, an3 * an3)));
#pragma unroll
    for (int o = 16; o; o >>= 1) {
        sap += __shfl_xor_sync(0xffffffffu, sap, o);
        san += __shfl_xor_sync(0xffffffffu, san, o);
    }
    if (lane == 0)
        shw[w] = fmaxf(sqrtf(sap) - sqrtf(san) + 0.3f, 0.f);
    __syncthreads();

    if (threadIdx.x == 0) {
        float s = 0.f;
#pragma unroll
        for (int i = 0; i < 8; i++) s += shw[i];
        g_partial[blockIdx.x] = s;
    }
    __threadfence();
    if (threadIdx.x == 0)
        amLast = (atomicInc(&g_cnt, 1023u) == 1023u);
    __syncthreads();

    if (amLast) {
        float s = 0.f;
        for (int i = threadIdx.x; i < 1024; i += 256) s += g_partial[i];
        shr[threadIdx.x] = s;
        __syncthreads();
        for (int o = 128; o; o >>= 1) {
            if (threadIdx.x < o) shr[threadIdx.x] += shr[threadIdx.x + o];
            __syncthreads();
        }
        if (threadIdx.x == 0) out[0] = shr[0] * (1.0f / N);
    }
}

// ---------------------------------------------------------------------------
extern "C" void kernel_launch(void* const* d_in, const int* in_sizes, int n_in,
                              void* d_out, int out_size) {
    const float* x   = (const float*)d_in[0];
    const float* pos = (const float*)d_in[1];
    float* out = (float*)d_out;

    cudaFuncSetAttribute(gram_top_kernel,
                         cudaFuncAttributeMaxDynamicSharedMemorySize, SM_TOTAL);

    prep_kernel<<<N / 8, 256>>>(x);
    gram_top_kernel<<<NTRI, 256, SM_TOTAL>>>();
    finalize_kernel<<<N / 8, 256>>>(x, pos, out);
}

// round 15
// speedup vs baseline: 1.6000x; 1.0272x over previous
#include <cuda_runtime.h>
#include <cuda_fp16.h>
#include <cstdint>

#define N 8192
#define D 128
#define NB 64                 // 64 blocks of 128 rows/cols
#define NTRI 2080             // NB*(NB+1)/2 tiles
#define STRB 272              // smem tile row stride bytes (136 halfs)

// dynamic smem layout (bytes)
#define SM_A     0            // 128*272 = 34816
#define SM_B     34816        // 34816
#define SM_SQR   69632        // 128 floats (row block norms+512)
#define SM_SQC   70144        // 128 floats (col block norms+512)
#define SM_P2    70656        // phase-2 col merge: 128*3 uints = 1536
#define SM_TOTAL 73728
#define SM_CSCR  0            // col scratch overlays A: 128*65*4 = 33280

__device__ __half   g_xh[N * D];
__device__ float    g_sq[N];            // ||x||^2 + 512
__device__ uint32_t g_keys[N][NB][3];   // per (row, block): top-3 slot keys
__device__ float    g_partial[1024];
__device__ unsigned g_cnt = 0;

__device__ __forceinline__ bool better(float d1, int i1, float d2, int i2) {
    return (d1 < d2) || (d1 == d2 && i1 < i2);
}
__device__ __forceinline__ uint32_t smem_u32(const void* p) {
    uint32_t a;
    asm("{ .reg .u64 t; cvta.to.shared.u64 t, %1; cvt.u32.u64 %0, t; }" : "=r"(a) : "l"(p));
    return a;
}
__device__ __forceinline__ void ldsm_x4(uint32_t* r, uint32_t addr) {
    asm volatile("ldmatrix.sync.aligned.m8n8.x4.shared.b16 {%0,%1,%2,%3}, [%4];"
                 : "=r"(r[0]), "=r"(r[1]), "=r"(r[2]), "=r"(r[3]) : "r"(addr));
}
__device__ __forceinline__ void mma16816(float* d, const uint32_t* a, uint32_t b0, uint32_t b1) {
    asm volatile("mma.sync.aligned.m16n8k16.row.col.f32.f16.f16.f32 "
                 "{%0,%1,%2,%3}, {%4,%5,%6,%7}, {%8,%9}, {%0,%1,%2,%3};"
                 : "+f"(d[0]), "+f"(d[1]), "+f"(d[2]), "+f"(d[3])
                 : "r"(a[0]), "r"(a[1]), "r"(a[2]), "r"(a[3]), "r"(b0), "r"(b1));
}
__device__ __forceinline__ void cp_async16(uint32_t dst, const void* src) {
    asm volatile("cp.async.cg.shared.global [%0], [%1], 16;" :: "r"(dst), "l"(src));
}
__device__ __forceinline__ void cp_commit() { asm volatile("cp.async.commit_group;" ::: "memory"); }
__device__ __forceinline__ void cp_wait0() { asm volatile("cp.async.wait_group 0;" ::: "memory"); }

// branchless depth-3 sorted insert on uint keys (6 ops)
__device__ __forceinline__ void ins3(uint32_t c, uint32_t* t) {
#pragma unroll
    for (int s = 0; s < 3; s++) {
        uint32_t lo = min(t[s], c);
        c = max(t[s], c);
        t[s] = lo;
    }
}

// ---------------------------------------------------------------------------
// Kernel P: fp16 cast + (row norm + 512), vectorized (LDG.128 + STG.64)
// ---------------------------------------------------------------------------
__global__ void prep_kernel(const float* __restrict__ x) {
    int row  = blockIdx.x * 8 + (threadIdx.x >> 5);
    int lane = threadIdx.x & 31;
    float4 v = ((const float4*)(x + row * D))[lane];
    __half2 h0 = __floats2half2_rn(v.x, v.y);
    __half2 h1 = __floats2half2_rn(v.z, v.w);
    uint2 packed = make_uint2(*(uint32_t*)&h0, *(uint32_t*)&h1);
    ((uint2*)(g_xh + row * D))[lane] = packed;
    float s = fmaf(v.x, v.x, fmaf(v.y, v.y, fmaf(v.z, v.z, v.w * v.w)));
#pragma unroll
    for (int o = 16; o; o >>= 1) s += __shfl_xor_sync(0xffffffffu, s, o);
    if (lane == 0) g_sq[row] = s + 512.0f;
}

// ---------------------------------------------------------------------------
// Kernel B: triangular fp16 Gram tiles (I<=J), dual-side slot selection.
// 2080 CTAs x 256 threads (8 warps, each 16 rows x 128 cols).
// Row-side: per row, top-3 quad-slots (4 cols each) -> g_keys[row][J].
// Col-side (I<J): per col, top-3 pair-slots (2 rows each) -> g_keys[col][I].
// Key = bits(sq_partner + 512 - 2*dot) truncated | id7.
// ---------------------------------------------------------------------------
__global__ __launch_bounds__(256, 2) void gram_top_kernel() {
    extern __shared__ char sm[];
    const uint32_t smBase = smem_u32(sm);
    float* sqR_sm = (float*)(sm + SM_SQR);
    float* sqC_sm = (float*)(sm + SM_SQC);

    const int tid = threadIdx.x;
    const int w = tid >> 5, l = tid & 31;
    const int lane2 = l & 3;

    // triangular tile index -> (I, J): closed form + 0/1-step fixup
    const int t = blockIdx.x;
    int I;
    {
        float ff = (129.0f - sqrtf(16641.0f - 8.0f * (float)t)) * 0.5f;
        I = (int)ff;
        I = max(0, min(I, NB - 1));
        while ((I + 1) * (129 - (I + 1)) / 2 <= t) I++;
        while (I * (129 - I) / 2 > t) I--;
    }
    const int J = I + (t - I * (129 - I) / 2);

    // load A (rows block I) and B (cols block J): 128 rows x 256 B each
    {
        const __half* Ag = g_xh + I * 128 * D;
        const __half* Bg = g_xh + J * 128 * D;
#pragma unroll
        for (int v = 0; v < 8; v++) {
            int i = tid + v * 256;            // 2048 16B chunks each
            int r = i >> 4, c16 = i & 15;
            cp_async16(smBase + SM_A + (uint32_t)(r * STRB + c16 * 16), Ag + r * D + c16 * 8);
            cp_async16(smBase + SM_B + (uint32_t)(r * STRB + c16 * 16), Bg + r * D + c16 * 8);
        }
        cp_commit();
        if (tid < 128) sqR_sm[tid] = g_sq[I * 128 + tid];
        else           sqC_sm[tid - 128] = g_sq[J * 128 + tid - 128];
        cp_wait0();
    }
    __syncthreads();

    // MMA: 16 rows x 128 cols per warp
    const uint32_t aBase = smBase + SM_A + (uint32_t)((w * 16 + (l & 15)) * STRB) + ((l >> 4) & 1) * 16;
    const uint32_t bBase = smBase + SM_B + (uint32_t)(((l & 7) + ((l >> 4) & 1) * 8) * STRB) + ((l >> 3) & 1) * 16;

    float acc[16][4];
#pragma unroll
    for (int nf = 0; nf < 16; nf++)
#pragma unroll
        for (int q = 0; q < 4; q++) acc[nf][q] = 0.f;

#pragma unroll
    for (int ks = 0; ks < 8; ks++) {
        uint32_t a[4];
        ldsm_x4(a, aBase + ks * 32);
#pragma unroll
        for (int nf4 = 0; nf4 < 8; nf4++) {
            uint32_t b[4];
            ldsm_x4(b, bBase + (uint32_t)(nf4 * 16 * STRB) + ks * 32);
            mma16816(acc[nf4 * 2],     a, b[0], b[1]);
            mma16816(acc[nf4 * 2 + 1], a, b[2], b[3]);
        }
    }

    const float sqRh0 = sqR_sm[w * 16 + (l >> 2)];
    const float sqRh1 = sqR_sm[w * 16 + (l >> 2) + 8];

    // ---- row-side: quad-slots {base, +1, +8, +9}, base = t8*16 + lane2*2 ----
    uint32_t kd[2][3];
#pragma unroll
    for (int h = 0; h < 2; h++)
#pragma unroll
        for (int s = 0; s < 3; s++) kd[h][s] = 0xFFFFFFFFu;

#pragma unroll
    for (int t8 = 0; t8 < 8; t8++) {
        float2 sjA = *(const float2*)&sqC_sm[t8 * 16 + lane2 * 2];
        float2 sjB = *(const float2*)&sqC_sm[t8 * 16 + 8 + lane2 * 2];
        const uint32_t idb = (uint32_t)((t8 << 2) | lane2);
#pragma unroll
        for (int h = 0; h < 2; h++) {
            float k0 = fmaf(-2.f, acc[2 * t8][h * 2 + 0], sjA.x);
            float k1 = fmaf(-2.f, acc[2 * t8][h * 2 + 1], sjA.y);
            float k2 = fmaf(-2.f, acc[2 * t8 + 1][h * 2 + 0], sjB.x);
            float k3 = fmaf(-2.f, acc[2 * t8 + 1][h * 2 + 1], sjB.y);
            float m = fminf(fminf(k0, k1), fminf(k2, k3));
            ins3((__float_as_uint(m) & 0xFFFFFF80u) | idb, kd[h]);
        }
    }
    // merge over the 4 lanes of each quad (rows identical within quad)
#pragma unroll
    for (int h = 0; h < 2; h++) {
#pragma unroll
        for (int off = 1; off < 4; off <<= 1) {
            uint32_t o[3];
#pragma unroll
            for (int s = 0; s < 3; s++) o[s] = __shfl_xor_sync(0xffffffffu, kd[h][s], off);
#pragma unroll
            for (int s = 0; s < 3; s++) ins3(o[s], kd[h]);
        }
    }
    if (lane2 == 0) {
#pragma unroll
        for (int h = 0; h < 2; h++) {
            int row = I * 128 + w * 16 + (l >> 2) + h * 8;
#pragma unroll
            for (int s = 0; s < 3; s++) g_keys[row][J][s] = kd[h][s];
        }
    }

    // ---- col-side (I < J): pair-slots {r, r+8} over rows ----
    if (I < J) {
        __syncthreads();   // all ldsm reads of A done; overlay scratch
        uint32_t* cscr = (uint32_t*)(sm + SM_CSCR);   // [128 cols][65] (padded)
        const uint32_t cid = (uint32_t)((w << 3) | (l >> 2));   // 6-bit slot id
#pragma unroll
        for (int nf = 0; nf < 16; nf++)
#pragma unroll
            for (int q = 0; q < 2; q++) {
                int c = nf * 8 + lane2 * 2 + q;
                float kk = fminf(fmaf(-2.f, acc[nf][q],     sqRh0),
                                 fmaf(-2.f, acc[nf][2 + q], sqRh1));
                cscr[c * 65 + cid] = (__float_as_uint(kk) & 0xFFFFFF80u) | cid;
            }
        __syncthreads();

        // phase 2: two threads per col, each reduces 32 of the 64 keys
        int c = tid & 127, half = tid >> 7;
        uint32_t t3[3] = {0xFFFFFFFFu, 0xFFFFFFFFu, 0xFFFFFFFFu};
#pragma unroll
        for (int k = 0; k < 32; k++) ins3(cscr[c * 65 + half * 32 + k], t3);
        uint32_t* p2 = (uint32_t*)(sm + SM_P2);
        if (half == 1) {
#pragma unroll
            for (int s = 0; s < 3; s++) p2[c * 3 + s] = t3[s];
        }
        __syncthreads();
        if (half == 0) {
#pragma unroll
            for (int s = 0; s < 3; s++) ins3(p2[c * 3 + s], t3);
            int col = J * 128 + c;
#pragma unroll
            for (int s = 0; s < 3; s++) g_keys[col][I][s] = t3[s];
        }
    }
}

// ---------------------------------------------------------------------------
// Kernel C: per-row 5th-smallest slot key over 192 keys, threshold-select,
// member expansion (quad row-side / pair col-side, exact prefix), 4-way
// interleaved exact rescore, lane-parallel top-5, hinge, fused mean.
// ---------------------------------------------------------------------------
__global__ void finalize_kernel(const float* __restrict__ x, const float* __restrict__ p,
                                float* __restrict__ out) {
    __shared__ int   memb[8][96];
    __shared__ float md2[8][96];
    __shared__ float shw[8];
    __shared__ float shr[256];
    __shared__ bool  amLast;
    int w    = threadIdx.x >> 5;
    int lane = threadIdx.x & 31;
    int row  = blockIdx.x * 8 + w;
    int Jr   = row >> 7;

    const uint32_t* kp = &g_keys[row][0][0];   // 192 keys
    uint32_t k[6];
#pragma unroll
    for (int v = 0; v < 6; v++) k[v] = kp[lane + 32 * v];

    // 5 extraction rounds -> 5th-smallest slot key (dupe removal biases up: safe)
    uint32_t a[6], gm = 0;
#pragma unroll
    for (int v = 0; v < 6; v++) a[v] = k[v];
#pragma unroll
    for (int r = 0; r < 5; r++) {
        uint32_t mv = a[0];
#pragma unroll
        for (int v = 1; v < 6; v++) mv = min(mv, a[v]);
#pragma unroll
        for (int o = 16; o; o >>= 1) mv = min(mv, __shfl_xor_sync(0xffffffffu, mv, o));
        gm = mv;
#pragma unroll
        for (int v = 0; v < 6; v++) if (a[v] == gm) a[v] = 0xFFFFFFFFu;
    }
    float thr = __uint_as_float(gm & 0xFFFFFF80u) + 1.0f;

    // compact passing slots -> expand members (4 row-side, 2 col-side)
    uint32_t ltm = (1u << lane) - 1u;
    int mtot = 0;
#pragma unroll
    for (int v = 0; v < 6; v++) {
        int kpos = lane + 32 * v;
        int bb = kpos / 3;
        bool quad = (bb >= Jr);
        bool pass = __uint_as_float(k[v] & 0xFFFFFF80u) <= thr;
        uint32_t balP = __ballot_sync(0xffffffffu, pass);
        uint32_t balQ = __ballot_sync(0xffffffffu, pass && quad);
        if (pass) {
            int pref = mtot + 4 * __popc(balQ & ltm) + 2 * __popc((balP & ~balQ) & ltm);
            if (pref < 92) {
                uint32_t id = k[v] & 0x7Fu;
                if (quad) {       // row-side quad: {0,1,8,9}
                    int base = bb * 128 + (int)((id >> 2) & 7) * 16 + (int)(id & 3) * 2;
                    memb[w][pref + 0] = base;
                    memb[w][pref + 1] = base + 1;
                    memb[w][pref + 2] = base + 8;
                    memb[w][pref + 3] = base + 9;
                } else {          // col-side pair: {0,8}
                    int base = bb * 128 + (int)((id >> 3) & 7) * 16 + (int)(id & 7);
                    memb[w][pref + 0] = base;
                    memb[w][pref + 1] = base + 8;
                }
            }
        }
        mtot += 4 * __popc(balQ) + 2 * __popc(balP & ~balQ);
    }
    int mcnt = min(mtot, 92);
    __syncwarp();

    float4 xi = ((const float4*)(x + row * D))[lane];

    // phase A: exact d^2 for all members, 4-way interleaved reductions
    for (int i = 0; i < mcnt; i += 4) {
        int j0 = memb[w][i];
        int j1 = memb[w][min(i + 1, mcnt - 1)];
        int j2 = memb[w][min(i + 2, mcnt - 1)];
        int j3 = memb[w][min(i + 3, mcnt - 1)];
        float4 xa = ((const float4*)(x + j0 * D))[lane];
        float4 xb = ((const float4*)(x + j1 * D))[lane];
        float4 xc = ((const float4*)(x + j2 * D))[lane];
        float4 xd = ((const float4*)(x + j3 * D))[lane];
        float a0 = xi.x - xa.x, a1 = xi.y - xa.y, a2 = xi.z - xa.z, a3 = xi.w - xa.w;
        float b0 = xi.x - xb.x, b1 = xi.y - xb.y, b2 = xi.z - xb.z, b3 = xi.w - xb.w;
        float c0 = xi.x - xc.x, c1 = xi.y - xc.y, c2 = xi.z - xc.z, c3 = xi.w - xc.w;
        float e0 = xi.x - xd.x, e1 = xi.y - xd.y, e2 = xi.z - xd.z, e3 = xi.w - xd.w;
        float s0 = fmaf(a0, a0, fmaf(a1, a1, fmaf(a2, a2, a3 * a3)));
        float s1 = fmaf(b0, b0, fmaf(b1, b1, fmaf(b2, b2, b3 * b3)));
        float s2 = fmaf(c0, c0, fmaf(c1, c1, fmaf(c2, c2, c3 * c3)));
        float s3 = fmaf(e0, e0, fmaf(e1, e1, fmaf(e2, e2, e3 * e3)));
#pragma unroll
        for (int o = 16; o; o >>= 1) {
            s0 += __shfl_xor_sync(0xffffffffu, s0, o);
            s1 += __shfl_xor_sync(0xffffffffu, s1, o);
            s2 += __shfl_xor_sync(0xffffffffu, s2, o);
            s3 += __shfl_xor_sync(0xffffffffu, s3, o);
        }
        if (lane == 0) {
            md2[w][i] = s0;
            if (i + 1 < mcnt) md2[w][i + 1] = s1;
            if (i + 2 < mcnt) md2[w][i + 2] = s2;
            if (i + 3 < mcnt) md2[w][i + 3] = s3;
        }
    }
    __syncwarp();

    // phase B: lane-parallel top-5 + butterfly merge (members are distinct)
    float t5d[5]; int t5i[5];
#pragma unroll
    for (int s = 0; s < 5; s++) { t5d[s] = __int_as_float(0x7f800000); t5i[s] = 0x7fffffff; }
    for (int i = lane; i < mcnt; i += 32) {
        float d2 = fmaxf(md2[w][i], 1e-12f);
        int j = memb[w][i];
        if (better(d2, j, t5d[4], t5i[4])) {
            float cd = d2; int ci = j;
#pragma unroll
            for (int s = 0; s < 5; s++) {
                if (better(cd, ci, t5d[s], t5i[s])) {
                    float td = t5d[s]; t5d[s] = cd; cd = td;
                    int   ti = t5i[s]; t5i[s] = ci; ci = ti;
                }
            }
        }
    }
#pragma unroll
    for (int off = 1; off < 32; off <<= 1) {
        float od[5]; int oi[5];
#pragma unroll
        for (int s = 0; s < 5; s++) {
            od[s] = __shfl_xor_sync(0xffffffffu, t5d[s], off);
            oi[s] = __shfl_xor_sync(0xffffffffu, t5i[s], off);
        }
        float ad[5]; int ai[5];
#pragma unroll
        for (int s = 0; s < 5; s++) { ad[s] = t5d[s]; ai[s] = t5i[s]; }
        int ia = 0, ib = 0;
#pragma unroll
        for (int s = 0; s < 5; s++) {
            bool ta = better(ad[ia], ai[ia], od[ib], oi[ib]);
            t5d[s] = ta ? ad[ia] : od[ib];
            t5i[s] = ta ? ai[ia] : oi[ib];
            if (ta) ia++; else ib++;
        }
    }
    int neg = t5i[4];

    float4 pi = ((const float4*)(p + row * D))[lane];
    float4 xn = ((const float4*)(x + neg * D))[lane];
    float ap0 = xi.x - pi.x + 1e-6f, ap1 = xi.y - pi.y + 1e-6f;
    float ap2 = xi.z - pi.z + 1e-6f, ap3 = xi.w - pi.w + 1e-6f;
    float an0 = xi.x - xn.x + 1e-6f, an1 = xi.y - xn.y + 1e-6f;
    float an2 = xi.z - xn.z + 1e-6f, an3 = xi.w - xn.w + 1e-6f;
    float sap = fmaf(ap0, ap0, fmaf(ap1, ap1, fmaf(ap2, ap2, ap3 * ap3)));
    float san = fmaf(an0, an0, fmaf(an1, an1, fmaf(an2, an2, an3 * an3)));
#pragma unroll
    for (int o = 16; o; o >>= 1) {
        sap += __shfl_xor_sync(0xffffffffu, sap, o);
        san += __shfl_xor_sync(0xffffffffu, san, o);
    }
    if (lane == 0)
        shw[w] = fmaxf(sqrtf(sap) - sqrtf(san) + 0.3f, 0.f);
    __syncthreads();

    if (threadIdx.x == 0) {
        float s = 0.f;
#pragma unroll
        for (int i = 0; i < 8; i++) s += shw[i];
        g_partial[blockIdx.x] = s;
    }
    __threadfence();
    if (threadIdx.x == 0)
        amLast = (atomicInc(&g_cnt, 1023u) == 1023u);
    __syncthreads();

    if (amLast) {
        float s = 0.f;
        for (int i = threadIdx.x; i < 1024; i += 256) s += g_partial[i];
        shr[threadIdx.x] = s;
        __syncthreads();
        for (int o = 128; o; o >>= 1) {
            if (threadIdx.x < o) shr[threadIdx.x] += shr[threadIdx.x + o];
            __syncthreads();
        }
        if (threadIdx.x == 0) out[0] = shr[0] * (1.0f / N);
    }
}

// ---------------------------------------------------------------------------
extern "C" void kernel_launch(void* const* d_in, const int* in_sizes, int n_in,
                              void* d_out, int out_size) {
    const float* x   = (const float*)d_in[0];
    const float* pos = (const float*)d_in[1];
    float* out = (float*)d_out;

    cudaFuncSetAttribute(gram_top_kernel,
                         cudaFuncAttributeMaxDynamicSharedMemorySize, SM_TOTAL);

    prep_kernel<<<N / 8, 256>>>(x);
    gram_top_kernel<<<NTRI, 256, SM_TOTAL>>>();
    finalize_kernel<<<N / 8, 256>>>(x, pos, out);
}